// round 6
// baseline (speedup 1.0000x reference)
#include <cuda_runtime.h>
#include <cuda_bf16.h>
#include <cstdint>

#define BSZ 32
#define HWPIX 409600
#define NPIX 13107200
#define HW4 102400            // float4 units per channel-plane (u64 scratch units per batch)
#define HW8 51200             // 8-pixel chunks per batch
#define NSCR (NPIX/4)         // u64 scratch entries (4 bf16 codes each)
#define NB1C 2048             // coarse bins = code >> 5
#define NB2 1024              // fine bins (bf16 codes within bracket)
#define MARGIN 100000LL       // rank-margin for sampled bracket (~9 sigma)
#define CT 409600             // k_collect total threads (NPIX/32)
#define NMAIN (HW8/256*BSZ)   // 6400 blocks in k_main
#define NCOLL (CT/256)        // 1600 blocks in k_collect

typedef unsigned long long u64;

// -------- device state (static; zero-init at load; self-cleaning) -------
__device__ __align__(16) u64 g_scratch[NSCR];   // 4 bf16 row-loss codes per entry (26MB)
__device__ unsigned int g_hist[NB1C];           // sampled coarse histogram
__device__ unsigned int g_fcnt[NB2];            // fine histogram counts
__device__ float        g_fsum[NB2];            // fine histogram value sums
__device__ double g_pos_loss;
__device__ double g_pos_w;
__device__ double g_sum_above;
__device__ unsigned int g_sumPos;
__device__ unsigned int g_cnt_above;
__device__ int g_blo, g_bhi, g_shift;
__device__ long long g_K;
__device__ unsigned int g_ctr_main;             // last-block-done counters
__device__ unsigned int g_ctr_coll;

// ---- packed f32x2 helpers ----
__device__ __forceinline__ u64 pk2(float a, float b) {
  u64 r; asm("mov.b64 %0, {%1, %2};" : "=l"(r) : "f"(a), "f"(b)); return r;
}
__device__ __forceinline__ void upk2(u64 v, float& a, float& b) {
  asm("mov.b64 {%0, %1}, %2;" : "=f"(a), "=f"(b) : "l"(v));
}
__device__ __forceinline__ u64 fma2(u64 a, u64 b, u64 c) {
  u64 d; asm("fma.rn.f32x2 %0, %1, %2, %3;" : "=l"(d) : "l"(a), "l"(b), "l"(c)); return d;
}
__device__ __forceinline__ u64 mul2(u64 a, u64 b) {
  u64 d; asm("mul.rn.f32x2 %0, %1, %2;" : "=l"(d) : "l"(a), "l"(b)); return d;
}
__device__ __forceinline__ u64 add2(u64 a, u64 b) {
  u64 d; asm("add.rn.f32x2 %0, %1, %2;" : "=l"(d) : "l"(a), "l"(b)); return d;
}
__device__ __forceinline__ unsigned cvt_bf2(float s0, float s1) {
  unsigned w;
  asm("cvt.rn.satfinite.bf16x2.f32 %0, %1, %2;" : "=r"(w) : "f"(s1), "f"(s0));
  return w;
}
__device__ __forceinline__ float bf2f(unsigned code) {
  return __uint_as_float(code << 16);
}

// ---------------------------------------------------------------
// Pass 1: per-pixel row loss -> bf16 codes (positives stored as code 0),
// positive sums, sampled coarse histogram. The LAST block to finish also
// computes K and the coarse bracket [blo,bhi] (former k_thresh).
__global__ void __launch_bounds__(256) k_main(const float4* __restrict__ pr,
                                              const float4* __restrict__ vm,
                                              const float4* __restrict__ wt) {
  __shared__ unsigned sh[NB1C];
  __shared__ float r_pl[8], r_pw[8];
  __shared__ unsigned r_np[8];
  __shared__ int s_last;
  for (int i = threadIdx.x; i < NB1C; i += 256) sh[i] = 0u;
  __syncthreads();
  const int b = blockIdx.y;
  const int i = blockIdx.x * 256 + threadIdx.x;     // [0, HW8)
  const int base = 2 * i;
  const float4* prb = pr + (size_t)b * 2 * HW4;
  const float4* vmb = vm + (size_t)b * 2 * HW4;
  const float4* wtb = wt + (size_t)b * HW4;
  float4 p0a = prb[base],       p0b = prb[base + 1];
  float4 p1a = prb[base + HW4], p1b = prb[base + HW4 + 1];
  float4 t0a = vmb[base],       t0b = vmb[base + 1];
  float4 t1a = vmb[base + HW4], t1b = vmb[base + HW4 + 1];
  float4 wa = wtb[base], wb = wtb[base + 1];
  const u64 M1 = pk2(-1.f, -1.f);
  u64 pl = 0ull, pw = 0ull;
  unsigned np = 0u;
  u64 d0 = fma2(pk2(t0a.x, t0a.y), M1, pk2(p0a.x, p0a.y));
  u64 d1 = fma2(pk2(t1a.x, t1a.y), M1, pk2(p1a.x, p1a.y));
  u64 se = fma2(d1, d1, mul2(d0, d0));
  u64 wv = pk2(wa.x, wa.y);
  pl = fma2(se, wv, pl); pw = add2(pw, wv);
  float s0, s1; upk2(se, s0, s1);
  unsigned wA = cvt_bf2(s0, s1);
  if (wa.x > 0.f) { wA &= 0xFFFF0000u; np++; }
  if (wa.y > 0.f) { wA &= 0x0000FFFFu; np++; }
  d0 = fma2(pk2(t0a.z, t0a.w), M1, pk2(p0a.z, p0a.w));
  d1 = fma2(pk2(t1a.z, t1a.w), M1, pk2(p1a.z, p1a.w));
  se = fma2(d1, d1, mul2(d0, d0));
  wv = pk2(wa.z, wa.w);
  pl = fma2(se, wv, pl); pw = add2(pw, wv);
  upk2(se, s0, s1);
  unsigned wB = cvt_bf2(s0, s1);
  if (wa.z > 0.f) { wB &= 0xFFFF0000u; np++; }
  if (wa.w > 0.f) { wB &= 0x0000FFFFu; np++; }
  d0 = fma2(pk2(t0b.x, t0b.y), M1, pk2(p0b.x, p0b.y));
  d1 = fma2(pk2(t1b.x, t1b.y), M1, pk2(p1b.x, p1b.y));
  se = fma2(d1, d1, mul2(d0, d0));
  wv = pk2(wb.x, wb.y);
  pl = fma2(se, wv, pl); pw = add2(pw, wv);
  upk2(se, s0, s1);
  unsigned wC = cvt_bf2(s0, s1);
  if (wb.x > 0.f) { wC &= 0xFFFF0000u; np++; }
  if (wb.y > 0.f) { wC &= 0x0000FFFFu; np++; }
  d0 = fma2(pk2(t0b.z, t0b.w), M1, pk2(p0b.z, p0b.w));
  d1 = fma2(pk2(t1b.z, t1b.w), M1, pk2(p1b.z, p1b.w));
  se = fma2(d1, d1, mul2(d0, d0));
  wv = pk2(wb.z, wb.w);
  pl = fma2(se, wv, pl); pw = add2(pw, wv);
  upk2(se, s0, s1);
  unsigned wD = cvt_bf2(s0, s1);
  if (wb.z > 0.f) { wD &= 0xFFFF0000u; np++; }
  if (wb.w > 0.f) { wD &= 0x0000FFFFu; np++; }

  if ((i & 7) == 0)                      // every 64th pixel
    atomicAdd(&sh[(wA & 0xFFFFu) >> 5], 1u);
  ulonglong2* s2b = (ulonglong2*)(g_scratch + (size_t)b * HW4);
  ulonglong2 outv;
  outv.x = (u64)wA | ((u64)wB << 32);
  outv.y = (u64)wC | ((u64)wD << 32);
  s2b[i] = outv;

  float pl0, pl1, pw0, pw1;
  upk2(pl, pl0, pl1); upk2(pw, pw0, pw1);
  float plf = pl0 + pl1, pwf = pw0 + pw1;
  for (int o = 16; o; o >>= 1) {
    plf += __shfl_down_sync(0xffffffffu, plf, o);
    pwf += __shfl_down_sync(0xffffffffu, pwf, o);
    np  += __shfl_down_sync(0xffffffffu, np, o);
  }
  int wid = threadIdx.x >> 5;
  if ((threadIdx.x & 31u) == 0u) { r_pl[wid] = plf; r_pw[wid] = pwf; r_np[wid] = np; }
  __syncthreads();
  if (threadIdx.x == 0) {
    float bpl = 0.f, bpw = 0.f; unsigned bnp = 0u;
#pragma unroll
    for (int k = 0; k < 8; k++) { bpl += r_pl[k]; bpw += r_pw[k]; bnp += r_np[k]; }
    if (bpl != 0.f) atomicAdd(&g_pos_loss, (double)bpl);
    if (bpw != 0.f) atomicAdd(&g_pos_w, (double)bpw);
    if (bnp) atomicAdd(&g_sumPos, bnp);
  }
  for (int k = threadIdx.x; k < NB1C; k += 256) {
    unsigned cnt = sh[k];
    if (cnt) atomicAdd(&g_hist[k], cnt);
  }
  // ---- last-block-done: compute K and coarse bracket ----
  __threadfence();
  if (threadIdx.x == 0)
    s_last = (atomicAdd(&g_ctr_main, 1u) == NMAIN - 1u);
  __syncthreads();
  if (!s_last) return;
  {
    __shared__ unsigned csum[256];
    __shared__ int s_blo, s_bhi;
    __shared__ long long sK;
    int t = threadIdx.x;
    if (t == 0) {
      long long sp = (long long)g_sumPos;
      long long K = 3 * sp;
      long long sn = (long long)NPIX - sp;
      if (K > sn) K = sn;
      sK = K; g_K = K;
      s_blo = 0; s_bhi = NB1C;
      g_ctr_main = 0u;                       // reset for next replay
    }
    __syncthreads();
    long long K = sK;
    int top = NB1C - 8 * t;
    unsigned cs[8]; unsigned s = 0;
#pragma unroll
    for (int j = 0; j < 8; j++) { cs[j] = g_hist[top - 1 - j]; s += cs[j]; }
    csum[t] = s;
    __syncthreads();
    for (int off = 1; off < 256; off <<= 1) {
      unsigned v = (t >= off) ? csum[t - off] : 0u;
      __syncthreads();
      csum[t] += v;
      __syncthreads();
    }
    unsigned long long run = (unsigned long long)csum[t] - s;
#pragma unroll
    for (int j = 0; j < 8; j++) {
      int bn = top - 1 - j;
      long long above = (long long)run * 64;
      run += cs[j];
      long long atb = (long long)run * 64;
      if (atb >= K + MARGIN) atomicMax(&s_blo, bn);
      if (above <= K - MARGIN) atomicMin(&s_bhi, bn);
    }
    __syncthreads();
    if (t == 0) {
      int blo = s_blo, bhi = s_bhi;
      if (bhi >= NB1C) bhi = NB1C - 1;
      if (bhi < blo) bhi = blo;
      long long range_codes = ((long long)(bhi - blo + 1)) << 5;
      int shift = 0;
      while ((range_codes >> shift) > NB2) shift++;
      g_blo = blo; g_bhi = bhi; g_shift = shift;
      __threadfence();
    }
  }
}

// ---------------------------------------------------------------
// Pass 2: scan scratch, exact sum/count above bracket + fine histogram of
// bracket values. 64-bit carry-trick tests 4 pixels per branch. The LAST
// block also runs the finalization (former k_final) and self-cleans.
__global__ void __launch_bounds__(256) k_collect(float* __restrict__ out) {
  __shared__ unsigned scnt[NB2];
  __shared__ float ssum[NB2];
  __shared__ int s_last;
  for (int i = threadIdx.x; i < NB2; i += 256) { scnt[i] = 0u; ssum[i] = 0.f; }
  __syncthreads();
  const int blo = g_blo, bhi = g_bhi, shift = g_shift;
  const unsigned lo_code = ((unsigned)blo) << 5;
  const unsigned hi_code = ((unsigned)(bhi + 1)) << 5;
  u64 addk4 = (u64)(0x8000u - lo_code);
  addk4 |= addk4 << 16; addk4 |= addk4 << 32;     // x4 halves; codes are 15-bit: no cross-lane carry
  const u64 MSB4 = 0x8000800080008000ull;
  const int tid = blockIdx.x * 256 + threadIdx.x;     // [0, CT)
  const ulonglong2* s2 = (const ulonglong2*)g_scratch;
  ulonglong2 v0 = s2[tid];
  ulonglong2 v1 = s2[tid + CT];
  ulonglong2 v2 = s2[tid + 2 * CT];
  ulonglong2 v3 = s2[tid + 3 * CT];
  u64 q[8] = {v0.x, v0.y, v1.x, v1.y, v2.x, v2.y, v3.x, v3.y};
  float sa = 0.f; unsigned ca = 0u;
#pragma unroll
  for (int j = 0; j < 8; j++) {
    if (((q[j] + addk4) & MSB4) != 0ull) {
      unsigned hw[2] = {(unsigned)q[j], (unsigned)(q[j] >> 32)};
#pragma unroll
      for (int k = 0; k < 2; k++) {
        unsigned h0 = hw[k] & 0xFFFFu;
        unsigned h1 = hw[k] >> 16;
        if (h0 >= hi_code) { sa += bf2f(h0); ca++; }
        else if (h0 >= lo_code) {
          unsigned key = (h0 - lo_code) >> shift;
          if (key >= NB2) key = NB2 - 1;
          atomicAdd(&scnt[key], 1u); atomicAdd(&ssum[key], bf2f(h0));
        }
        if (h1 >= hi_code) { sa += bf2f(h1); ca++; }
        else if (h1 >= lo_code) {
          unsigned key = (h1 - lo_code) >> shift;
          if (key >= NB2) key = NB2 - 1;
          atomicAdd(&scnt[key], 1u); atomicAdd(&ssum[key], bf2f(h1));
        }
      }
    }
  }
  for (int o = 16; o; o >>= 1) {
    sa += __shfl_down_sync(0xffffffffu, sa, o);
    ca += __shfl_down_sync(0xffffffffu, ca, o);
  }
  __shared__ float r_sa[8];
  __shared__ unsigned r_ca[8];
  int wid = threadIdx.x >> 5;
  if ((threadIdx.x & 31u) == 0u) { r_sa[wid] = sa; r_ca[wid] = ca; }
  __syncthreads();
  if (threadIdx.x == 0) {
    float bs = 0.f; unsigned bc = 0u;
#pragma unroll
    for (int k = 0; k < 8; k++) { bs += r_sa[k]; bc += r_ca[k]; }
    if (bs != 0.f) atomicAdd(&g_sum_above, (double)bs);
    if (bc) atomicAdd(&g_cnt_above, bc);
  }
  for (int i = threadIdx.x; i < NB2; i += 256) {
    unsigned c = scnt[i];
    if (c) { atomicAdd(&g_fcnt[i], c); atomicAdd(&g_fsum[i], ssum[i]); }
  }
  // ---- last-block-done: finalize loss + self-clean ----
  __threadfence();
  if (threadIdx.x == 0)
    s_last = (atomicAdd(&g_ctr_coll, 1u) == NCOLL - 1u);
  __syncthreads();
  if (!s_last) return;
  {
    __shared__ unsigned csum[256];
    __shared__ double red[256];
    int t = threadIdx.x;
    long long K = g_K;
    long long r = K - (long long)g_cnt_above;
    if (r < 0) r = 0;
    int top = NB2 - 4 * t;
    unsigned cs[4]; float fs[4]; unsigned s = 0;
#pragma unroll
    for (int j = 0; j < 4; j++) {
      int bn = top - 1 - j;
      cs[j] = g_fcnt[bn]; fs[j] = g_fsum[bn]; s += cs[j];
    }
    csum[t] = s;
    __syncthreads();
    for (int off = 1; off < 256; off <<= 1) {
      unsigned v = (t >= off) ? csum[t - off] : 0u;
      __syncthreads();
      csum[t] += v;
      __syncthreads();
    }
    unsigned long long run = (unsigned long long)csum[t] - s;
    double c = 0.0;
#pragma unroll
    for (int j = 0; j < 4; j++) {
      long long need = r - (long long)run;
      if (need <= 0) break;
      unsigned cnt = cs[j];
      if ((long long)cnt <= need) c += (double)fs[j];
      else if (cnt > 0u) c += (double)need * (double)fs[j] / (double)cnt;
      run += cnt;
    }
    red[t] = c;
    __syncthreads();
    for (int off = 128; off; off >>= 1) {
      if (t < off) red[t] += red[t + off];
      __syncthreads();
    }
    if (t == 0) {
      double total = g_pos_loss + g_sum_above + red[0];
      double denom = 2.0 * g_pos_w + 2.0 * (double)K;
      out[0] = (float)(total / denom / (double)BSZ);
    }
    __syncthreads();
    // self-clean for next replay
    for (int i = t; i < NB1C; i += 256) g_hist[i] = 0u;
    for (int i = t; i < NB2; i += 256) { g_fcnt[i] = 0u; g_fsum[i] = 0.f; }
    if (t == 0) {
      g_pos_loss = 0.0; g_pos_w = 0.0; g_sum_above = 0.0;
      g_sumPos = 0u; g_cnt_above = 0u; g_ctr_coll = 0u;
    }
  }
}

// ---------------------------------------------------------------
extern "C" void kernel_launch(void* const* d_in, const int* in_sizes, int n_in,
                              void* d_out, int out_size) {
  (void)in_sizes; (void)n_in; (void)out_size;
  const float4* pr = (const float4*)d_in[0];
  const float4* vm = (const float4*)d_in[1];
  const float4* wt = (const float4*)d_in[2];
  float* out = (float*)d_out;
  k_main<<<dim3(HW8 / 256, BSZ), 256>>>(pr, vm, wt);
  k_collect<<<NCOLL, 256>>>(out);
}

// round 7
// speedup vs baseline: 1.1752x; 1.1752x over previous
#include <cuda_runtime.h>
#include <cstdint>

#define BSZ 32
#define NPIX 13107200
#define HW4 102400            // float4 units per channel-plane per batch
#define HW8 51200             // 8-pixel chunks per batch
#define NCHUNK 1638400        // NPIX/8 total 8-pixel chunks
#define NB 32768              // full bf16-code histogram (15-bit codes)
#define GRID_H 152            // persistent: 1 block per SM (GB300 = 152 SMs)
#define THR_H 768
#define STRIDE_H (GRID_H*THR_H)
#define THR_F 1024

typedef unsigned long long u64;

// -------- device state (zero-init at load; k_final self-cleans) -------
__device__ unsigned int g_hist32[NB];
__device__ double g_pos_loss;
__device__ double g_pos_w;
__device__ unsigned int g_sumPos;

// ---- packed f32x2 helpers ----
__device__ __forceinline__ u64 pk2(float a, float b) {
  u64 r; asm("mov.b64 %0, {%1, %2};" : "=l"(r) : "f"(a), "f"(b)); return r;
}
__device__ __forceinline__ void upk2(u64 v, float& a, float& b) {
  asm("mov.b64 {%0, %1}, %2;" : "=f"(a), "=f"(b) : "l"(v));
}
__device__ __forceinline__ u64 fma2(u64 a, u64 b, u64 c) {
  u64 d; asm("fma.rn.f32x2 %0, %1, %2, %3;" : "=l"(d) : "l"(a), "l"(b), "l"(c)); return d;
}
__device__ __forceinline__ u64 mul2(u64 a, u64 b) {
  u64 d; asm("mul.rn.f32x2 %0, %1, %2;" : "=l"(d) : "l"(a), "l"(b)); return d;
}
__device__ __forceinline__ u64 add2(u64 a, u64 b) {
  u64 d; asm("add.rn.f32x2 %0, %1, %2;" : "=l"(d) : "l"(a), "l"(b)); return d;
}
// two f32 -> bf16x2 word (lo = s0, hi = s1), round-to-nearest-even
__device__ __forceinline__ unsigned cvt_bf2(float s0, float s1) {
  unsigned w;
  asm("cvt.rn.satfinite.bf16x2.f32 %0, %1, %2;" : "=r"(w) : "f"(s1), "f"(s0));
  return w;
}
__device__ __forceinline__ float bf2f(unsigned code) {
  return __uint_as_float(code << 16);
}

// ---------------------------------------------------------------
// Single data pass: per-pixel row loss -> bf16 code (positives forced to
// code 0), full 32768-bin count histogram privatized in 128KB dynamic
// smem (1 block/SM, persistent), positive sums block-reduced.
// The histogram is a lossless sufficient statistic for the top-K sum:
// all members of a bin share the same (bf16) value.
__global__ void __launch_bounds__(THR_H) k_hist(const float4* __restrict__ pr,
                                                const float4* __restrict__ vm,
                                                const float4* __restrict__ wt) {
  extern __shared__ unsigned hist[];          // NB counts
  for (int i = threadIdx.x; i < NB; i += THR_H) hist[i] = 0u;
  __syncthreads();
  const u64 M1 = pk2(-1.f, -1.f);
  u64 pl = 0ull, pw = 0ull;
  unsigned np = 0u;
  for (int c = blockIdx.x * THR_H + threadIdx.x; c < NCHUNK; c += STRIDE_H) {
    int b = c / HW8;
    int i = c - b * HW8;
    int base = 2 * i;
    const float4* prb = pr + (size_t)b * 2 * HW4;
    const float4* vmb = vm + (size_t)b * 2 * HW4;
    const float4* wtb = wt + (size_t)b * HW4;
    float4 p0a = prb[base],       p0b = prb[base + 1];
    float4 p1a = prb[base + HW4], p1b = prb[base + HW4 + 1];
    float4 t0a = vmb[base],       t0b = vmb[base + 1];
    float4 t1a = vmb[base + HW4], t1b = vmb[base + HW4 + 1];
    float4 wa = wtb[base], wb = wtb[base + 1];
    // pair (px0,px1)
    u64 d0 = fma2(pk2(t0a.x, t0a.y), M1, pk2(p0a.x, p0a.y));
    u64 d1 = fma2(pk2(t1a.x, t1a.y), M1, pk2(p1a.x, p1a.y));
    u64 se = fma2(d1, d1, mul2(d0, d0));
    u64 wv = pk2(wa.x, wa.y);
    pl = fma2(se, wv, pl); pw = add2(pw, wv);
    float s0, s1; upk2(se, s0, s1);
    unsigned wA = cvt_bf2(s0, s1);
    if (wa.x > 0.f) { wA &= 0xFFFF0000u; np++; }
    if (wa.y > 0.f) { wA &= 0x0000FFFFu; np++; }
    // pair (px2,px3)
    d0 = fma2(pk2(t0a.z, t0a.w), M1, pk2(p0a.z, p0a.w));
    d1 = fma2(pk2(t1a.z, t1a.w), M1, pk2(p1a.z, p1a.w));
    se = fma2(d1, d1, mul2(d0, d0));
    wv = pk2(wa.z, wa.w);
    pl = fma2(se, wv, pl); pw = add2(pw, wv);
    upk2(se, s0, s1);
    unsigned wB = cvt_bf2(s0, s1);
    if (wa.z > 0.f) { wB &= 0xFFFF0000u; np++; }
    if (wa.w > 0.f) { wB &= 0x0000FFFFu; np++; }
    // pair (px4,px5)
    d0 = fma2(pk2(t0b.x, t0b.y), M1, pk2(p0b.x, p0b.y));
    d1 = fma2(pk2(t1b.x, t1b.y), M1, pk2(p1b.x, p1b.y));
    se = fma2(d1, d1, mul2(d0, d0));
    wv = pk2(wb.x, wb.y);
    pl = fma2(se, wv, pl); pw = add2(pw, wv);
    upk2(se, s0, s1);
    unsigned wC = cvt_bf2(s0, s1);
    if (wb.x > 0.f) { wC &= 0xFFFF0000u; np++; }
    if (wb.y > 0.f) { wC &= 0x0000FFFFu; np++; }
    // pair (px6,px7)
    d0 = fma2(pk2(t0b.z, t0b.w), M1, pk2(p0b.z, p0b.w));
    d1 = fma2(pk2(t1b.z, t1b.w), M1, pk2(p1b.z, p1b.w));
    se = fma2(d1, d1, mul2(d0, d0));
    wv = pk2(wb.z, wb.w);
    pl = fma2(se, wv, pl); pw = add2(pw, wv);
    upk2(se, s0, s1);
    unsigned wD = cvt_bf2(s0, s1);
    if (wb.z > 0.f) { wD &= 0xFFFF0000u; np++; }
    if (wb.w > 0.f) { wD &= 0x0000FFFFu; np++; }
    // 8 shared-atomic increments (codes are 15-bit; positives land in bin 0,
    // whose value is 0 so it never affects the top-K sum)
    atomicAdd(&hist[wA & 0xFFFFu], 1u);
    atomicAdd(&hist[wA >> 16], 1u);
    atomicAdd(&hist[wB & 0xFFFFu], 1u);
    atomicAdd(&hist[wB >> 16], 1u);
    atomicAdd(&hist[wC & 0xFFFFu], 1u);
    atomicAdd(&hist[wC >> 16], 1u);
    atomicAdd(&hist[wD & 0xFFFFu], 1u);
    atomicAdd(&hist[wD >> 16], 1u);
  }
  // block reduction of positive sums
  float pl0, pl1, pw0, pw1;
  upk2(pl, pl0, pl1); upk2(pw, pw0, pw1);
  float plf = pl0 + pl1, pwf = pw0 + pw1;
  for (int o = 16; o; o >>= 1) {
    plf += __shfl_down_sync(0xffffffffu, plf, o);
    pwf += __shfl_down_sync(0xffffffffu, pwf, o);
    np  += __shfl_down_sync(0xffffffffu, np, o);
  }
  __shared__ float r_pl[THR_H / 32], r_pw[THR_H / 32];
  __shared__ unsigned r_np[THR_H / 32];
  int wid = threadIdx.x >> 5;
  if ((threadIdx.x & 31u) == 0u) { r_pl[wid] = plf; r_pw[wid] = pwf; r_np[wid] = np; }
  __syncthreads();
  if (threadIdx.x == 0) {
    float bpl = 0.f, bpw = 0.f; unsigned bnp = 0u;
#pragma unroll
    for (int k = 0; k < THR_H / 32; k++) { bpl += r_pl[k]; bpw += r_pw[k]; bnp += r_np[k]; }
    if (bpl != 0.f) atomicAdd(&g_pos_loss, (double)bpl);
    if (bpw != 0.f) atomicAdd(&g_pos_w, (double)bpw);
    if (bnp) atomicAdd(&g_sumPos, bnp);
  }
  // flush nonzero bins to global
  for (int i = threadIdx.x; i < NB; i += THR_H) {
    unsigned cv = hist[i];
    if (cv) atomicAdd(&g_hist32[i], cv);
  }
}

// ---------------------------------------------------------------
// Finalize: 1 block, 1024 threads, 32 descending bins per thread.
// Block-wide descending prefix scan of counts locates the K-th largest;
// top-K sum is exact: sum(count*value) with partial take in the boundary
// bin (all members of a bin have identical value). Self-cleans state.
__global__ void __launch_bounds__(THR_F) k_final(float* __restrict__ out) {
  int t = threadIdx.x;
  int top = NB - 32 * t;                     // thread 0 owns the highest codes
  unsigned cs[32]; unsigned s = 0;
#pragma unroll
  for (int j = 0; j < 32; j++) { cs[j] = g_hist32[top - 1 - j]; s += cs[j]; }
  // block exclusive scan (thread order == descending code order)
  __shared__ unsigned wsum[32];
  unsigned lane = t & 31u, wid = t >> 5;
  unsigned incl = s;
  for (int o = 1; o < 32; o <<= 1) {
    unsigned v = __shfl_up_sync(0xffffffffu, incl, o);
    if (lane >= o) incl += v;
  }
  if (lane == 31u) wsum[wid] = incl;
  __syncthreads();
  if (wid == 0) {
    unsigned wv = wsum[lane];
    unsigned wincl = wv;
    for (int o = 1; o < 32; o <<= 1) {
      unsigned x = __shfl_up_sync(0xffffffffu, wincl, o);
      if (lane >= o) wincl += x;
    }
    wsum[lane] = wincl - wv;                 // exclusive warp offsets
  }
  __syncthreads();
  unsigned long long run = (unsigned long long)wsum[wid] + (incl - s);
  long long sp = (long long)g_sumPos;
  long long K = 3 * sp;
  long long sn = (long long)NPIX - sp;
  if (K > sn) K = sn;
  double acc = 0.0;
#pragma unroll
  for (int j = 0; j < 32; j++) {
    long long need = K - (long long)run;
    if (need <= 0) break;
    unsigned cnt = cs[j];
    if (cnt) {
      long long take = ((long long)cnt <= need) ? (long long)cnt : need;
      acc += (double)bf2f((unsigned)(top - 1 - j)) * (double)take;
    }
    run += cnt;
  }
  // block double reduction
  for (int o = 16; o; o >>= 1)
    acc += __shfl_down_sync(0xffffffffu, acc, o);
  __shared__ double dsum[32];
  if (lane == 0u) dsum[wid] = acc;
  __syncthreads();
  if (t == 0) {
    double total = g_pos_loss;
#pragma unroll
    for (int k = 0; k < 32; k++) total += dsum[k];
    double denom = 2.0 * g_pos_w + 2.0 * (double)K;
    out[0] = (float)(total / denom / (double)BSZ);
  }
  // ---- self-clean for next replay ----
  for (int i = t; i < NB; i += THR_F) g_hist32[i] = 0u;
  if (t == 0) { g_pos_loss = 0.0; g_pos_w = 0.0; g_sumPos = 0u; }
}

// ---------------------------------------------------------------
extern "C" void kernel_launch(void* const* d_in, const int* in_sizes, int n_in,
                              void* d_out, int out_size) {
  (void)in_sizes; (void)n_in; (void)out_size;
  const float4* pr = (const float4*)d_in[0];
  const float4* vm = (const float4*)d_in[1];
  const float4* wt = (const float4*)d_in[2];
  float* out = (float*)d_out;
  cudaFuncSetAttribute(k_hist, cudaFuncAttributeMaxDynamicSharedMemorySize, NB * 4);
  k_hist<<<GRID_H, THR_H, NB * 4>>>(pr, vm, wt);
  k_final<<<1, THR_F>>>(out);
}